// round 5
// baseline (speedup 1.0000x reference)
#include <cuda_runtime.h>
#include <cuda_bf16.h>
#include <math.h>
#include <stdint.h>

// ---------------------------------------------------------------------------
// GatedDeltaNetVarlen — round 5:
//   * mma.sync bf16-split GEMM, cp.async 3-stage pipeline, tiles loaded ONCE
//     per K-chunk with all 3 split-combos issued from register fragments
//   * ba projections folded into the fused GEMM (padded 128-col range)
//   * recurrence with depth-2 register prefetch (hides L2 latency)
// ---------------------------------------------------------------------------

#define TOTAL_MAX 1536
#define HIDDEN    1024
#define CONV_DIM  2048
#define KEY_DIM   512
#define VAL_DIM   1024
#define HV        16
#define GK        1024
#define SSTR      40                  // smem row stride (bf16), conflict-free
#define TSZ       (128 * SSTR)        // elements per tile
#define GEMM_SMEM (3 * 4 * TSZ * 2)   // 3 stages x 4 tiles x 128x40 bf16 = 122880 B

typedef __nv_bfloat16 bf16;

__device__ float g_mixed[TOTAL_MAX * CONV_DIM];
__device__ float g_qkv  [TOTAL_MAX * CONV_DIM];
__device__ float g_z    [TOTAL_MAX * VAL_DIM];
__device__ float g_c3   [TOTAL_MAX * 128];
__device__ float g_beta [TOTAL_MAX * HV];
__device__ float g_gate [TOTAL_MAX * HV];
__device__ float g_o    [TOTAL_MAX * VAL_DIM];

__device__ bf16 g_hs_h  [TOTAL_MAX * HIDDEN];
__device__ bf16 g_hs_l  [TOTAL_MAX * HIDDEN];
__device__ bf16 g_wqkv_h[CONV_DIM * HIDDEN];
__device__ bf16 g_wqkv_l[CONV_DIM * HIDDEN];
__device__ bf16 g_wz_h  [VAL_DIM * HIDDEN];
__device__ bf16 g_wz_l  [VAL_DIM * HIDDEN];
__device__ bf16 g_wba_h [128 * HIDDEN];
__device__ bf16 g_wba_l [128 * HIDDEN];
__device__ bf16 g_wout_h[HIDDEN * VAL_DIM];
__device__ bf16 g_wout_l[HIDDEN * VAL_DIM];
__device__ bf16 g_on_h  [TOTAL_MAX * VAL_DIM];
__device__ bf16 g_on_l  [TOTAL_MAX * VAL_DIM];

// ---------------------------------------------------------------------------
// helpers
// ---------------------------------------------------------------------------
__device__ __forceinline__ void ldsm_x4(unsigned& r0, unsigned& r1, unsigned& r2, unsigned& r3,
                                        const bf16* p)
{
    unsigned addr = (unsigned)__cvta_generic_to_shared(p);
    asm volatile("ldmatrix.sync.aligned.m8n8.x4.shared.b16 {%0,%1,%2,%3}, [%4];"
                 : "=r"(r0), "=r"(r1), "=r"(r2), "=r"(r3) : "r"(addr));
}

__device__ __forceinline__ void mma16816(float* c, const unsigned* a, const unsigned* b)
{
    asm volatile(
        "mma.sync.aligned.m16n8k16.row.col.f32.bf16.bf16.f32 "
        "{%0,%1,%2,%3},{%4,%5,%6,%7},{%8,%9},{%0,%1,%2,%3};\n"
        : "+f"(c[0]), "+f"(c[1]), "+f"(c[2]), "+f"(c[3])
        : "r"(a[0]), "r"(a[1]), "r"(a[2]), "r"(a[3]), "r"(b[0]), "r"(b[1]));
}

__device__ __forceinline__ void cp16(const bf16* dst_smem, const bf16* src)
{
    unsigned d = (unsigned)__cvta_generic_to_shared(dst_smem);
    asm volatile("cp.async.cg.shared.global [%0], [%1], 16;" :: "r"(d), "l"(src));
}
#define CP_COMMIT() asm volatile("cp.async.commit_group;")
template<int N> __device__ __forceinline__ void cp_wait() {
    asm volatile("cp.async.wait_group %0;" :: "n"(N));
}

// ---------------------------------------------------------------------------
// Triple-range bf16-split GEMM:  C = A[M,1024] @ B[N,1024]^T
//   pass-shared SMEM: per K-chunk load Ah,Al,Bh,Bl once; acc += hh + lh + hl.
// BM=BN=128, BK=32, 256 threads (8 warps 4x2), warp tile 32x64.
// 3-stage cp.async pipeline, 1 barrier per chunk.
// ---------------------------------------------------------------------------
__global__ __launch_bounds__(256) void gemm_mma3(
    const bf16* __restrict__ Ah, const bf16* __restrict__ Al,
    const bf16* __restrict__ B1h, const bf16* __restrict__ B1l,
    const bf16* __restrict__ B2h, const bf16* __restrict__ B2l,
    const bf16* __restrict__ B3h, const bf16* __restrict__ B3l,
    float* __restrict__ C1, float* __restrict__ C2, float* __restrict__ C3,
    int N1, int N2, int N3)
{
    extern __shared__ bf16 smem[];

    const int tid  = threadIdx.x;
    const int lane = tid & 31;
    const int wid  = tid >> 5;
    const int wm   = wid & 3;
    const int wn   = wid >> 2;
    const int bm   = blockIdx.y * 128;
    const int bnG  = blockIdx.x * 128;

    const bf16* Bh; const bf16* Bl; float* C; int bn, ldc;
    if (bnG < N1)           { Bh = B1h; Bl = B1l; C = C1; bn = bnG;           ldc = N1; }
    else if (bnG < N1 + N2) { Bh = B2h; Bl = B2l; C = C2; bn = bnG - N1;      ldc = N2; }
    else                    { Bh = B3h; Bl = B3l; C = C3; bn = bnG - N1 - N2; ldc = N3; }

    const bf16* srcs[4] = { Ah, Al, Bh, Bl };
    const int   rb[4]   = { bm, bm, bn, bn };

    // loader mapping: per tile, 512 x 16B transfers, 2 per thread
    const int li0 = tid, li1 = tid + 256;
    const int lr0 = li0 >> 2, lc0 = (li0 & 3) * 8;
    const int lr1 = li1 >> 2, lc1 = (li1 & 3) * 8;

    float c[2][8][4];
#pragma unroll
    for (int mi = 0; mi < 2; mi++)
#pragma unroll
        for (int ni = 0; ni < 8; ni++)
#pragma unroll
            for (int r = 0; r < 4; r++) c[mi][ni][r] = 0.f;

    const int NC = GK / 32;   // 32 chunks

    // ---- load chunk ck into stage st ----
    auto load_chunk = [&](int st, int ck) {
        const int k0 = ck * 32;
#pragma unroll
        for (int t = 0; t < 4; t++) {
            bf16* tb = smem + (st * 4 + t) * TSZ;
            const bf16* s = srcs[t];
            cp16(tb + lr0 * SSTR + lc0, s + (size_t)(rb[t] + lr0) * GK + k0 + lc0);
            cp16(tb + lr1 * SSTR + lc1, s + (size_t)(rb[t] + lr1) * GK + k0 + lc1);
        }
    };

    load_chunk(0, 0); CP_COMMIT();
    load_chunk(1, 1); CP_COMMIT();

    const int lrow16 = lane & 15;
    const int lhalf  = lane >> 4;
    const int l8     = lane & 7;
    const int grp    = lane >> 3;

#pragma unroll 1
    for (int ck = 0; ck < NC; ck++) {
        if (ck + 1 < NC) cp_wait<1>(); else cp_wait<0>();
        __syncthreads();

        if (ck + 2 < NC) { load_chunk((ck + 2) % 3, ck + 2); CP_COMMIT(); }

        const bf16* Asb = smem + (ck % 3) * 4 * TSZ;
        const bf16* Alb = Asb + TSZ;
        const bf16* Bhb = Asb + 2 * TSZ;
        const bf16* Blb = Asb + 3 * TSZ;

#pragma unroll
        for (int kk = 0; kk < 32; kk += 16) {
            unsigned ah[2][4], al[2][4];
#pragma unroll
            for (int mi = 0; mi < 2; mi++) {
                const int ar = (wm * 32 + mi * 16 + lrow16) * SSTR + kk + 8 * lhalf;
                ldsm_x4(ah[mi][0], ah[mi][1], ah[mi][2], ah[mi][3], Asb + ar);
                ldsm_x4(al[mi][0], al[mi][1], al[mi][2], al[mi][3], Alb + ar);
            }
#pragma unroll
            for (int nj = 0; nj < 4; nj++) {
                unsigned bh[2][2], bl[2][2];
                const int br = (wn * 64 + nj * 16 + (grp >> 1) * 8 + l8) * SSTR
                             + kk + 8 * (grp & 1);
                ldsm_x4(bh[0][0], bh[0][1], bh[1][0], bh[1][1], Bhb + br);
                ldsm_x4(bl[0][0], bl[0][1], bl[1][0], bl[1][1], Blb + br);
#pragma unroll
                for (int mi = 0; mi < 2; mi++)
#pragma unroll
                    for (int nn = 0; nn < 2; nn++) {
                        float* cc = c[mi][nj * 2 + nn];
                        mma16816(cc, ah[mi], bh[nn]);
                        mma16816(cc, al[mi], bh[nn]);
                        mma16816(cc, ah[mi], bl[nn]);
                    }
            }
        }
    }

    const int g  = lane >> 2;
    const int t4 = lane & 3;
#pragma unroll
    for (int mi = 0; mi < 2; mi++) {
        const int row0 = bm + wm * 32 + mi * 16 + g;
#pragma unroll
        for (int ni = 0; ni < 8; ni++) {
            const int col = bn + wn * 64 + ni * 8 + 2 * t4;
            *(float2*)(C + (size_t)row0 * ldc + col)       = make_float2(c[mi][ni][0], c[mi][ni][1]);
            *(float2*)(C + (size_t)(row0 + 8) * ldc + col) = make_float2(c[mi][ni][2], c[mi][ni][3]);
        }
    }
}

// ---------------------------------------------------------------------------
// Vectorized fp32 -> (hi,lo) bf16 split
// ---------------------------------------------------------------------------
__global__ __launch_bounds__(256) void split4_kernel(
    const float4* __restrict__ x, uint2* __restrict__ h, uint2* __restrict__ l, int n4)
{
    int i = blockIdx.x * blockDim.x + threadIdx.x;
    if (i >= n4) return;
    float4 v = x[i];
    bf16 h0 = __float2bfloat16(v.x), h1 = __float2bfloat16(v.y);
    bf16 h2 = __float2bfloat16(v.z), h3 = __float2bfloat16(v.w);
    bf16 l0 = __float2bfloat16(v.x - __bfloat162float(h0));
    bf16 l1 = __float2bfloat16(v.y - __bfloat162float(h1));
    bf16 l2 = __float2bfloat16(v.z - __bfloat162float(h2));
    bf16 l3 = __float2bfloat16(v.w - __bfloat162float(h3));
    uint2 hv, lv;
    hv.x = ((unsigned)__bfloat16_as_ushort(h1) << 16) | __bfloat16_as_ushort(h0);
    hv.y = ((unsigned)__bfloat16_as_ushort(h3) << 16) | __bfloat16_as_ushort(h2);
    lv.x = ((unsigned)__bfloat16_as_ushort(l1) << 16) | __bfloat16_as_ushort(l0);
    lv.y = ((unsigned)__bfloat16_as_ushort(l3) << 16) | __bfloat16_as_ushort(l2);
    h[i] = hv;
    l[i] = lv;
}

// Build padded [W_b ; W_a ; zeros] 128x1024 split weight
__global__ __launch_bounds__(256) void split_wba_kernel(
    const float* __restrict__ Wb, const float* __restrict__ Wa,
    bf16* __restrict__ h, bf16* __restrict__ l)
{
    int i = blockIdx.x * blockDim.x + threadIdx.x;
    float v = 0.f;
    if (i < 16 * HIDDEN)      v = Wb[i];
    else if (i < 32 * HIDDEN) v = Wa[i - 16 * HIDDEN];
    bf16 hh = __float2bfloat16(v);
    h[i] = hh;
    l[i] = __float2bfloat16(v - __bfloat162float(hh));
}

// beta / gate from the GEMM's third range
__global__ __launch_bounds__(256) void ba_finish_kernel(
    const float* __restrict__ c3, const float* __restrict__ dtb,
    const float* __restrict__ Alog, float* __restrict__ beta, float* __restrict__ gate,
    int total)
{
    int idx = blockIdx.x * blockDim.x + threadIdx.x;
    int t = idx >> 5;
    int o = idx & 31;
    if (t >= total) return;
    float x = c3[(size_t)t * 128 + o];
    if (o < HV) {
        beta[(size_t)t * HV + o] = 1.f / (1.f + expf(-x));
    } else {
        int hh = o - HV;
        float xv = x + dtb[hh];
        float sp = (xv > 20.f) ? xv : log1pf(expf(xv));
        gate[(size_t)t * HV + hh] = -expf(Alog[hh]) * sp;
    }
}

// ---------------------------------------------------------------------------
// Fused causal depthwise conv(4) + silu + per-head q/k L2 norm
// ---------------------------------------------------------------------------
__global__ __launch_bounds__(256) void conv_norm_kernel(
    const float* __restrict__ mixed, const float* __restrict__ cw,
    const int* __restrict__ cu, int B, float* __restrict__ out)
{
    const int t = blockIdx.x;
    const int tid = threadIdx.x;
    const int c0 = tid * 8;

    int start = 0;
    for (int i = 1; i < B; i++) { int s = cu[i]; if (t >= s) start = s; }

    float y[8];
#pragma unroll
    for (int j = 0; j < 8; j++) {
        const int c = c0 + j;
        const float4 w4 = *(const float4*)(cw + c * 4);
        float acc = mixed[(size_t)t * CONV_DIM + c] * w4.w;
        if (t - 1 >= start) acc = fmaf(mixed[(size_t)(t - 1) * CONV_DIM + c], w4.z, acc);
        if (t - 2 >= start) acc = fmaf(mixed[(size_t)(t - 2) * CONV_DIM + c], w4.y, acc);
        if (t - 3 >= start) acc = fmaf(mixed[(size_t)(t - 3) * CONV_DIM + c], w4.x, acc);
        y[j] = acc / (1.f + expf(-acc));
    }

    if (c0 < 2 * KEY_DIM) {
        float ss = 0.f;
#pragma unroll
        for (int j = 0; j < 8; j++) ss = fmaf(y[j], y[j], ss);
        ss += __shfl_xor_sync(0xffffffffu, ss, 1);
        ss += __shfl_xor_sync(0xffffffffu, ss, 2);
        ss += __shfl_xor_sync(0xffffffffu, ss, 4);
        float r = rsqrtf(ss + 1e-6f);
        if (c0 < KEY_DIM) r *= 0.125f;
#pragma unroll
        for (int j = 0; j < 8; j++) y[j] *= r;
    }

    float4* dst = (float4*)(out + (size_t)t * CONV_DIM + c0);
    dst[0] = make_float4(y[0], y[1], y[2], y[3]);
    dst[1] = make_float4(y[4], y[5], y[6], y[7]);
}

// ---------------------------------------------------------------------------
// Gated delta rule recurrence, depth-2 register prefetch.
// ---------------------------------------------------------------------------
__global__ __launch_bounds__(256) void recurrence_kernel(
    const float* __restrict__ qkv, const float* __restrict__ beta,
    const float* __restrict__ gate, const int* __restrict__ cu,
    float* __restrict__ O)
{
    const int b = blockIdx.x >> 4;
    const int h = blockIdx.x & 15;
    const int start = cu[b];
    const int end   = cu[b + 1];

    const int tid = threadIdx.x;
    const int v  = tid >> 2;
    const int kh = tid & 3;

    const int qoff = (h >> 1) * 64;
    const int koff = KEY_DIM + (h >> 1) * 64;
    const int voff = 2 * KEY_DIM + h * 64;

    float S[16];
#pragma unroll
    for (int i = 0; i < 16; i++) S[i] = 0.f;

    __shared__ float sk[2][64];
    __shared__ float sq[2][64];

    float rk[2], rq[2], vv[2], ge[2], bb[2];
#pragma unroll
    for (int j = 0; j < 2; j++) { rk[j] = rq[j] = vv[j] = ge[j] = bb[j] = 0.f; }

#pragma unroll
    for (int j = 0; j < 2; j++) {
        const int t = start + j;
        if (t < end) {
            const int sl = t & 1;
            const float* __restrict__ row = qkv + (size_t)t * CONV_DIM;
            if (tid < 64)       rk[sl] = row[koff + tid];
            else if (tid < 128) rq[sl] = row[qoff + tid - 64];
            ge[sl] = expf(gate[(size_t)t * HV + h]);
            bb[sl] = beta[(size_t)t * HV + h];
            vv[sl] = row[voff + v];
        }
    }

    for (int t = start; t < end; t++) {
        const int sl = t & 1;
        if (tid < 64)       sk[sl][tid]      = rk[sl];
        else if (tid < 128) sq[sl][tid - 64] = rq[sl];

        const float cg = ge[sl], cb = bb[sl], cv = vv[sl];

        if (t + 2 < end) {
            const float* __restrict__ nrow = qkv + (size_t)(t + 2) * CONV_DIM;
            if (tid < 64)       rk[sl] = nrow[koff + tid];
            else if (tid < 128) rq[sl] = nrow[qoff + tid - 64];
            ge[sl] = expf(gate[(size_t)(t + 2) * HV + h]);
            bb[sl] = beta[(size_t)(t + 2) * HV + h];
            vv[sl] = nrow[voff + v];
        }
        __syncthreads();

        float kf[16], qf[16];
        const float4* k4 = (const float4*)(sk[sl] + kh * 16);
        const float4* q4 = (const float4*)(sq[sl] + kh * 16);
#pragma unroll
        for (int j = 0; j < 4; j++) {
            float4 kv4 = k4[j]; float4 qv4 = q4[j];
            kf[4*j+0]=kv4.x; kf[4*j+1]=kv4.y; kf[4*j+2]=kv4.z; kf[4*j+3]=kv4.w;
            qf[4*j+0]=qv4.x; qf[4*j+1]=qv4.y; qf[4*j+2]=qv4.z; qf[4*j+3]=qv4.w;
        }

        float dk0=0,dk1=0,dk2=0,dk3=0, dq0=0,dq1=0,dq2=0,dq3=0, qk0=0,qk1=0,qk2=0,qk3=0;
#pragma unroll
        for (int j = 0; j < 4; j++) {
            dk0 = fmaf(kf[4*j+0], S[4*j+0], dk0);
            dk1 = fmaf(kf[4*j+1], S[4*j+1], dk1);
            dk2 = fmaf(kf[4*j+2], S[4*j+2], dk2);
            dk3 = fmaf(kf[4*j+3], S[4*j+3], dk3);
            dq0 = fmaf(qf[4*j+0], S[4*j+0], dq0);
            dq1 = fmaf(qf[4*j+1], S[4*j+1], dq1);
            dq2 = fmaf(qf[4*j+2], S[4*j+2], dq2);
            dq3 = fmaf(qf[4*j+3], S[4*j+3], dq3);
            qk0 = fmaf(qf[4*j+0], kf[4*j+0], qk0);
            qk1 = fmaf(qf[4*j+1], kf[4*j+1], qk1);
            qk2 = fmaf(qf[4*j+2], kf[4*j+2], qk2);
            qk3 = fmaf(qf[4*j+3], kf[4*j+3], qk3);
        }
        float dk = (dk0 + dk1) + (dk2 + dk3);
        float dq = (dq0 + dq1) + (dq2 + dq3);
        float qk = (qk0 + qk1) + (qk2 + qk3);

        dk += __shfl_xor_sync(0xffffffffu, dk, 1);
        dq += __shfl_xor_sync(0xffffffffu, dq, 1);
        qk += __shfl_xor_sync(0xffffffffu, qk, 1);
        dk += __shfl_xor_sync(0xffffffffu, dk, 2);
        dq += __shfl_xor_sync(0xffffffffu, dq, 2);
        qk += __shfl_xor_sync(0xffffffffu, qk, 2);

        const float kv    = cg * dk;
        const float delta = cb * (cv - kv);

#pragma unroll
        for (int i = 0; i < 16; i++)
            S[i] = fmaf(kf[i], delta, cg * S[i]);

        if (kh == 0) {
            const float o = fmaf(qk, delta, cg * dq);
            O[(size_t)t * VAL_DIM + h * 64 + v] = o;
        }
    }
}

// ---------------------------------------------------------------------------
// Gated RMSNorm fused with bf16 split
// ---------------------------------------------------------------------------
__global__ __launch_bounds__(512) void rmsnorm_split_kernel(
    const float* __restrict__ o, const float* __restrict__ z,
    const float* __restrict__ nw, bf16* __restrict__ onh, bf16* __restrict__ onl)
{
    const int t = blockIdx.x;
    const int w = threadIdx.x >> 5;
    const int lane = threadIdx.x & 31;
    const size_t base = (size_t)t * VAL_DIM + w * 64;

    float x0 = o[base + lane];
    float x1 = o[base + 32 + lane];
    float ss = x0 * x0 + x1 * x1;
#pragma unroll
    for (int off = 16; off; off >>= 1)
        ss += __shfl_xor_sync(0xffffffffu, ss, off);
    float r = rsqrtf(ss * (1.f / 64.f) + 1e-6f);

    float z0 = z[base + lane];
    float z1 = z[base + 32 + lane];
    float s0 = z0 / (1.f + expf(-z0));
    float s1 = z1 / (1.f + expf(-z1));

    float v0 = x0 * r * nw[lane]      * s0;
    float v1 = x1 * r * nw[lane + 32] * s1;

    bf16 h0 = __float2bfloat16(v0);
    bf16 h1 = __float2bfloat16(v1);
    onh[base + lane]      = h0;
    onh[base + 32 + lane] = h1;
    onl[base + lane]      = __float2bfloat16(v0 - __bfloat162float(h0));
    onl[base + 32 + lane] = __float2bfloat16(v1 - __bfloat162float(h1));
}

// ---------------------------------------------------------------------------
extern "C" void kernel_launch(void* const* d_in, const int* in_sizes, int n_in,
                              void* d_out, int out_size)
{
    const float* hs     = (const float*)d_in[0];
    const float* W_qkv  = (const float*)d_in[1];
    const float* W_z    = (const float*)d_in[2];
    const float* W_b    = (const float*)d_in[3];
    const float* W_a    = (const float*)d_in[4];
    const float* conv_w = (const float*)d_in[5];
    const float* dt_b   = (const float*)d_in[6];
    const float* A_log  = (const float*)d_in[7];
    const float* norm_w = (const float*)d_in[8];
    const float* W_out  = (const float*)d_in[9];
    const int*   cu     = (const int*)d_in[10];

    const int total = in_sizes[0] / HIDDEN;       // 1536
    const int B     = in_sizes[10] - 1;           // 4

    float *mixed, *qkv, *zbuf, *c3, *betab, *gateb, *obuf;
    bf16 *hs_h, *hs_l, *wqkv_h, *wqkv_l, *wz_h, *wz_l, *wba_h, *wba_l,
         *wout_h, *wout_l, *on_h, *on_l;
    cudaGetSymbolAddress((void**)&mixed,  g_mixed);
    cudaGetSymbolAddress((void**)&qkv,    g_qkv);
    cudaGetSymbolAddress((void**)&zbuf,   g_z);
    cudaGetSymbolAddress((void**)&c3,     g_c3);
    cudaGetSymbolAddress((void**)&betab,  g_beta);
    cudaGetSymbolAddress((void**)&gateb,  g_gate);
    cudaGetSymbolAddress((void**)&obuf,   g_o);
    cudaGetSymbolAddress((void**)&hs_h,   g_hs_h);
    cudaGetSymbolAddress((void**)&hs_l,   g_hs_l);
    cudaGetSymbolAddress((void**)&wqkv_h, g_wqkv_h);
    cudaGetSymbolAddress((void**)&wqkv_l, g_wqkv_l);
    cudaGetSymbolAddress((void**)&wz_h,   g_wz_h);
    cudaGetSymbolAddress((void**)&wz_l,   g_wz_l);
    cudaGetSymbolAddress((void**)&wba_h,  g_wba_h);
    cudaGetSymbolAddress((void**)&wba_l,  g_wba_l);
    cudaGetSymbolAddress((void**)&wout_h, g_wout_h);
    cudaGetSymbolAddress((void**)&wout_l, g_wout_l);
    cudaGetSymbolAddress((void**)&on_h,   g_on_h);
    cudaGetSymbolAddress((void**)&on_l,   g_on_l);

    cudaFuncSetAttribute(gemm_mma3, cudaFuncAttributeMaxDynamicSharedMemorySize, GEMM_SMEM);

    // 0-4) splits
    split4_kernel<<<(total * HIDDEN / 4 + 255) / 256, 256>>>(
        (const float4*)hs, (uint2*)hs_h, (uint2*)hs_l, total * HIDDEN / 4);
    split4_kernel<<<(CONV_DIM * HIDDEN / 4 + 255) / 256, 256>>>(
        (const float4*)W_qkv, (uint2*)wqkv_h, (uint2*)wqkv_l, CONV_DIM * HIDDEN / 4);
    split4_kernel<<<(VAL_DIM * HIDDEN / 4 + 255) / 256, 256>>>(
        (const float4*)W_z, (uint2*)wz_h, (uint2*)wz_l, VAL_DIM * HIDDEN / 4);
    split4_kernel<<<(HIDDEN * VAL_DIM / 4 + 255) / 256, 256>>>(
        (const float4*)W_out, (uint2*)wout_h, (uint2*)wout_l, HIDDEN * VAL_DIM / 4);
    split_wba_kernel<<<(128 * HIDDEN + 255) / 256, 256>>>(W_b, W_a, wba_h, wba_l);

    // 5) fused projections: [W_qkv | W_z | W_ba-padded] -> mixed, z, c3
    gemm_mma3<<<dim3((CONV_DIM + VAL_DIM + 128) / 128, total / 128), 256, GEMM_SMEM>>>(
        hs_h, hs_l, wqkv_h, wqkv_l, wz_h, wz_l, wba_h, wba_l,
        mixed, zbuf, c3, CONV_DIM, VAL_DIM, 128);

    // 6) beta / gate
    ba_finish_kernel<<<(total * 32 + 255) / 256, 256>>>(c3, dt_b, A_log, betab, gateb, total);

    // 7) fused causal conv + silu + qk norm
    conv_norm_kernel<<<total, 256>>>(mixed, conv_w, cu, B, qkv);

    // 8) gated delta rule recurrence
    recurrence_kernel<<<B * HV, 256>>>(qkv, betab, gateb, cu, obuf);

    // 9) gated RMSNorm + split
    rmsnorm_split_kernel<<<total, 512>>>(obuf, zbuf, norm_w, on_h, on_l);

    // 10) output projection -> d_out
    gemm_mma3<<<dim3(HIDDEN / 128, total / 128), 256, GEMM_SMEM>>>(
        on_h, on_l, wout_h, wout_l, wout_h, wout_l, wout_h, wout_l,
        (float*)d_out, (float*)d_out, (float*)d_out, HIDDEN, 0, 0);
}

// round 6
// speedup vs baseline: 1.6568x; 1.6568x over previous
#include <cuda_runtime.h>
#include <cuda_bf16.h>
#include <math.h>
#include <stdint.h>

// ---------------------------------------------------------------------------
// GatedDeltaNetVarlen — round 6:
//   * GEMM: exact R3 ldmatrix/mma.sync 2-stage kernel (proven 110us), now
//     with a third N-range folding in the b/a projections
//   * recurrence: cp.async 5-slot ring (depth-4), HW-guaranteed load overlap,
//     one barrier per step, dq/qk reductions off the critical path
// ---------------------------------------------------------------------------

#define TOTAL_MAX 1536
#define HIDDEN    1024
#define CONV_DIM  2048
#define KEY_DIM   512
#define VAL_DIM   1024
#define HV        16
#define GK        1024
#define SSTR      40     // smem row stride (bf16), conflict-free for LDSM

typedef __nv_bfloat16 bf16;

__device__ float g_mixed[TOTAL_MAX * CONV_DIM];
__device__ float g_qkv  [TOTAL_MAX * CONV_DIM];
__device__ float g_z    [TOTAL_MAX * VAL_DIM];
__device__ float g_c3   [TOTAL_MAX * 128];
__device__ float g_beta [TOTAL_MAX * HV];
__device__ float g_gate [TOTAL_MAX * HV];
__device__ float g_o    [TOTAL_MAX * VAL_DIM];

__device__ bf16 g_hs_h  [TOTAL_MAX * HIDDEN];
__device__ bf16 g_hs_l  [TOTAL_MAX * HIDDEN];
__device__ bf16 g_wqkv_h[CONV_DIM * HIDDEN];
__device__ bf16 g_wqkv_l[CONV_DIM * HIDDEN];
__device__ bf16 g_wz_h  [VAL_DIM * HIDDEN];
__device__ bf16 g_wz_l  [VAL_DIM * HIDDEN];
__device__ bf16 g_wba_h [128 * HIDDEN];
__device__ bf16 g_wba_l [128 * HIDDEN];
__device__ bf16 g_wout_h[HIDDEN * VAL_DIM];
__device__ bf16 g_wout_l[HIDDEN * VAL_DIM];
__device__ bf16 g_on_h  [TOTAL_MAX * VAL_DIM];
__device__ bf16 g_on_l  [TOTAL_MAX * VAL_DIM];

// ---------------------------------------------------------------------------
// helpers
// ---------------------------------------------------------------------------
__device__ __forceinline__ void ldsm_x4(unsigned& r0, unsigned& r1, unsigned& r2, unsigned& r3,
                                        const bf16* p)
{
    unsigned addr = (unsigned)__cvta_generic_to_shared(p);
    asm volatile("ldmatrix.sync.aligned.m8n8.x4.shared.b16 {%0,%1,%2,%3}, [%4];"
                 : "=r"(r0), "=r"(r1), "=r"(r2), "=r"(r3) : "r"(addr));
}

__device__ __forceinline__ void mma16816(float* c, const unsigned* a, const unsigned* b)
{
    asm volatile(
        "mma.sync.aligned.m16n8k16.row.col.f32.bf16.bf16.f32 "
        "{%0,%1,%2,%3},{%4,%5,%6,%7},{%8,%9},{%0,%1,%2,%3};\n"
        : "+f"(c[0]), "+f"(c[1]), "+f"(c[2]), "+f"(c[3])
        : "r"(a[0]), "r"(a[1]), "r"(a[2]), "r"(a[3]), "r"(b[0]), "r"(b[1]));
}

__device__ __forceinline__ void cp16f(const float* dst_smem, const float* src)
{
    unsigned d = (unsigned)__cvta_generic_to_shared(dst_smem);
    asm volatile("cp.async.cg.shared.global [%0], [%1], 16;" :: "r"(d), "l"(src));
}
__device__ __forceinline__ void cp4f(const float* dst_smem, const float* src)
{
    unsigned d = (unsigned)__cvta_generic_to_shared(dst_smem);
    asm volatile("cp.async.ca.shared.global [%0], [%1], 4;" :: "r"(d), "l"(src));
}
#define CP_COMMIT() asm volatile("cp.async.commit_group;")
template<int N> __device__ __forceinline__ void cp_wait() {
    asm volatile("cp.async.wait_group %0;" :: "n"(N));
}

// ---------------------------------------------------------------------------
// bf16 split GEMM, triple N-range (exact R3 structure):
//   cols [0,N1): C1 = A@B1^T ; [N1,N1+N2): C2 ; [N1+N2, +N3): C3
// 3 passes (hh, lh, hl), BM=BN=128, BK=32, 256 thr, warp tile 32x64, LDSM.
// ---------------------------------------------------------------------------
__global__ __launch_bounds__(256) void gemm_bf16split_tri(
    const bf16* __restrict__ Ah, const bf16* __restrict__ Al,
    const bf16* __restrict__ B1h, const bf16* __restrict__ B1l,
    const bf16* __restrict__ B2h, const bf16* __restrict__ B2l,
    const bf16* __restrict__ B3h, const bf16* __restrict__ B3l,
    float* __restrict__ C1, float* __restrict__ C2, float* __restrict__ C3,
    int N1, int N2, int N3)
{
    __shared__ bf16 As[2][128][SSTR];
    __shared__ bf16 Bs[2][128][SSTR];

    const int tid  = threadIdx.x;
    const int lane = tid & 31;
    const int wid  = tid >> 5;
    const int wm   = wid & 3;
    const int wn   = wid >> 2;
    const int bm   = blockIdx.y * 128;
    const int bnG  = blockIdx.x * 128;

    const bf16* Bh; const bf16* Bl; float* C; int bn, ldc;
    if (bnG < N1)           { Bh = B1h; Bl = B1l; C = C1; bn = bnG;           ldc = N1; }
    else if (bnG < N1 + N2) { Bh = B2h; Bl = B2l; C = C2; bn = bnG - N1;      ldc = N2; }
    else                    { Bh = B3h; Bl = B3l; C = C3; bn = bnG - N1 - N2; ldc = N3; }

    const int lrow = tid >> 2;
    const int lcol = (tid & 3) * 8;

    const bf16* APs[3] = { Ah, Al, Ah };
    const bf16* BPs[3] = { Bh, Bh, Bl };

    float c[2][8][4];
#pragma unroll
    for (int mi = 0; mi < 2; mi++)
#pragma unroll
        for (int ni = 0; ni < 8; ni++)
#pragma unroll
            for (int r = 0; r < 4; r++) c[mi][ni][r] = 0.f;

    const int NIT = 3 * (GK / 32);

    {
        uint4 pa0 = *(const uint4*)(APs[0] + (size_t)(bm + lrow) * GK + lcol);
        uint4 pa1 = *(const uint4*)(APs[0] + (size_t)(bm + lrow + 64) * GK + lcol);
        uint4 pb0 = *(const uint4*)(BPs[0] + (size_t)(bn + lrow) * GK + lcol);
        uint4 pb1 = *(const uint4*)(BPs[0] + (size_t)(bn + lrow + 64) * GK + lcol);
        *(uint4*)&As[0][lrow][lcol]      = pa0;
        *(uint4*)&As[0][lrow + 64][lcol] = pa1;
        *(uint4*)&Bs[0][lrow][lcol]      = pb0;
        *(uint4*)&Bs[0][lrow + 64][lcol] = pb1;
    }
    __syncthreads();

    const int lrow16 = lane & 15;
    const int lhalf  = lane >> 4;
    const int l8     = lane & 7;
    const int grp    = lane >> 3;

    for (int it = 0; it < NIT; ++it) {
        const int cur = it & 1;
        const bool has_next = (it + 1 < NIT);

        uint4 pa0, pa1, pb0, pb1;
        if (has_next) {
            const int nit = it + 1;
            const int p  = nit >> 5;
            const int k0 = (nit & 31) * 32;
            pa0 = *(const uint4*)(APs[p] + (size_t)(bm + lrow) * GK + k0 + lcol);
            pa1 = *(const uint4*)(APs[p] + (size_t)(bm + lrow + 64) * GK + k0 + lcol);
            pb0 = *(const uint4*)(BPs[p] + (size_t)(bn + lrow) * GK + k0 + lcol);
            pb1 = *(const uint4*)(BPs[p] + (size_t)(bn + lrow + 64) * GK + k0 + lcol);
        }

#pragma unroll
        for (int kk = 0; kk < 32; kk += 16) {
            unsigned a[2][4];
#pragma unroll
            for (int mi = 0; mi < 2; mi++)
                ldsm_x4(a[mi][0], a[mi][1], a[mi][2], a[mi][3],
                        &As[cur][wm * 32 + mi * 16 + lrow16][kk + 8 * lhalf]);
            unsigned b[8][2];
#pragma unroll
            for (int nj = 0; nj < 4; nj++)
                ldsm_x4(b[2 * nj][0], b[2 * nj][1], b[2 * nj + 1][0], b[2 * nj + 1][1],
                        &Bs[cur][wn * 64 + nj * 16 + (grp >> 1) * 8 + l8][kk + 8 * (grp & 1)]);
#pragma unroll
            for (int mi = 0; mi < 2; mi++)
#pragma unroll
                for (int ni = 0; ni < 8; ni++)
                    mma16816(c[mi][ni], a[mi], b[ni]);
        }

        if (has_next) {
            const int nxt = cur ^ 1;
            *(uint4*)&As[nxt][lrow][lcol]      = pa0;
            *(uint4*)&As[nxt][lrow + 64][lcol] = pa1;
            *(uint4*)&Bs[nxt][lrow][lcol]      = pb0;
            *(uint4*)&Bs[nxt][lrow + 64][lcol] = pb1;
            __syncthreads();
        }
    }

    const int g  = lane >> 2;
    const int t4 = lane & 3;
#pragma unroll
    for (int mi = 0; mi < 2; mi++) {
        const int row0 = bm + wm * 32 + mi * 16 + g;
#pragma unroll
        for (int ni = 0; ni < 8; ni++) {
            const int col = bn + wn * 64 + ni * 8 + 2 * t4;
            *(float2*)(C + (size_t)row0 * ldc + col)       = make_float2(c[mi][ni][0], c[mi][ni][1]);
            *(float2*)(C + (size_t)(row0 + 8) * ldc + col) = make_float2(c[mi][ni][2], c[mi][ni][3]);
        }
    }
}

// ---------------------------------------------------------------------------
// Vectorized fp32 -> (hi,lo) bf16 split
// ---------------------------------------------------------------------------
__device__ __forceinline__ void split_one4(float4 v, uint2* h, uint2* l, int i)
{
    bf16 h0 = __float2bfloat16(v.x), h1 = __float2bfloat16(v.y);
    bf16 h2 = __float2bfloat16(v.z), h3 = __float2bfloat16(v.w);
    bf16 l0 = __float2bfloat16(v.x - __bfloat162float(h0));
    bf16 l1 = __float2bfloat16(v.y - __bfloat162float(h1));
    bf16 l2 = __float2bfloat16(v.z - __bfloat162float(h2));
    bf16 l3 = __float2bfloat16(v.w - __bfloat162float(h3));
    uint2 hv, lv;
    hv.x = ((unsigned)__bfloat16_as_ushort(h1) << 16) | __bfloat16_as_ushort(h0);
    hv.y = ((unsigned)__bfloat16_as_ushort(h3) << 16) | __bfloat16_as_ushort(h2);
    lv.x = ((unsigned)__bfloat16_as_ushort(l1) << 16) | __bfloat16_as_ushort(l0);
    lv.y = ((unsigned)__bfloat16_as_ushort(l3) << 16) | __bfloat16_as_ushort(l2);
    h[i] = hv;
    l[i] = lv;
}

__global__ __launch_bounds__(256) void split4_kernel(
    const float4* __restrict__ x, uint2* __restrict__ h, uint2* __restrict__ l, int n4)
{
    int i = blockIdx.x * blockDim.x + threadIdx.x;
    if (i >= n4) return;
    split_one4(x[i], h, l, i);
}

// Combined split of W_z, W_out, and padded [W_b;W_a;0] (one launch)
#define NZ4  (VAL_DIM * HIDDEN / 4)
#define NO4  (HIDDEN * VAL_DIM / 4)
#define NBA4 (128 * HIDDEN / 4)
__global__ __launch_bounds__(256) void split_weights2_kernel(
    const float4* __restrict__ wz, const float4* __restrict__ wout,
    const float* __restrict__ Wb, const float* __restrict__ Wa,
    uint2* __restrict__ wzh, uint2* __restrict__ wzl,
    uint2* __restrict__ wouth, uint2* __restrict__ woutl,
    uint2* __restrict__ wbah, uint2* __restrict__ wbal)
{
    int i = blockIdx.x * blockDim.x + threadIdx.x;
    if (i < NZ4) {
        split_one4(wz[i], wzh, wzl, i);
    } else if (i < NZ4 + NO4) {
        int j = i - NZ4;
        split_one4(wout[j], wouth, woutl, j);
    } else if (i < NZ4 + NO4 + NBA4) {
        int j = i - NZ4 - NO4;           // float4 index into 128x1024
        int e = j * 4;
        float4 v;
        if (e < 16 * HIDDEN)      v = *(const float4*)(Wb + e);
        else if (e < 32 * HIDDEN) v = *(const float4*)(Wa + e - 16 * HIDDEN);
        else                      v = make_float4(0.f, 0.f, 0.f, 0.f);
        split_one4(v, wbah, wbal, j);
    }
}

// beta / gate from the GEMM's third range
__global__ __launch_bounds__(256) void ba_finish_kernel(
    const float* __restrict__ c3, const float* __restrict__ dtb,
    const float* __restrict__ Alog, float* __restrict__ beta, float* __restrict__ gate,
    int total)
{
    int idx = blockIdx.x * blockDim.x + threadIdx.x;
    int t = idx >> 5;
    int o = idx & 31;
    if (t >= total) return;
    float x = c3[(size_t)t * 128 + o];
    if (o < HV) {
        beta[(size_t)t * HV + o] = 1.f / (1.f + expf(-x));
    } else {
        int hh = o - HV;
        float xv = x + dtb[hh];
        float sp = (xv > 20.f) ? xv : log1pf(expf(xv));
        gate[(size_t)t * HV + hh] = -expf(Alog[hh]) * sp;
    }
}

// ---------------------------------------------------------------------------
// Fused causal depthwise conv(4) + silu + per-head q/k L2 norm
// ---------------------------------------------------------------------------
__global__ __launch_bounds__(256) void conv_norm_kernel(
    const float* __restrict__ mixed, const float* __restrict__ cw,
    const int* __restrict__ cu, int B, float* __restrict__ out)
{
    const int t = blockIdx.x;
    const int tid = threadIdx.x;
    const int c0 = tid * 8;

    int start = 0;
    for (int i = 1; i < B; i++) { int s = cu[i]; if (t >= s) start = s; }

    float y[8];
#pragma unroll
    for (int j = 0; j < 8; j++) {
        const int c = c0 + j;
        const float4 w4 = *(const float4*)(cw + c * 4);
        float acc = mixed[(size_t)t * CONV_DIM + c] * w4.w;
        if (t - 1 >= start) acc = fmaf(mixed[(size_t)(t - 1) * CONV_DIM + c], w4.z, acc);
        if (t - 2 >= start) acc = fmaf(mixed[(size_t)(t - 2) * CONV_DIM + c], w4.y, acc);
        if (t - 3 >= start) acc = fmaf(mixed[(size_t)(t - 3) * CONV_DIM + c], w4.x, acc);
        y[j] = acc / (1.f + expf(-acc));
    }

    if (c0 < 2 * KEY_DIM) {
        float ss = 0.f;
#pragma unroll
        for (int j = 0; j < 8; j++) ss = fmaf(y[j], y[j], ss);
        ss += __shfl_xor_sync(0xffffffffu, ss, 1);
        ss += __shfl_xor_sync(0xffffffffu, ss, 2);
        ss += __shfl_xor_sync(0xffffffffu, ss, 4);
        float r = rsqrtf(ss + 1e-6f);
        if (c0 < KEY_DIM) r *= 0.125f;
#pragma unroll
        for (int j = 0; j < 8; j++) y[j] *= r;
    }

    float4* dst = (float4*)(out + (size_t)t * CONV_DIM + c0);
    dst[0] = make_float4(y[0], y[1], y[2], y[3]);
    dst[1] = make_float4(y[4], y[5], y[6], y[7]);
}

// ---------------------------------------------------------------------------
// Gated delta rule recurrence with cp.async 5-slot ring (depth-4 overlap).
// One block per (seq,head), 256 threads (v=tid>>2, kh=tid&3).
// Per step: wait ring slot -> barrier -> issue refill (slot-1) -> compute.
// Only dk is on the critical path; dq/qk reduced after the S update.
// ---------------------------------------------------------------------------
#define RING 5
__global__ __launch_bounds__(256) void recurrence_kernel(
    const float* __restrict__ qkv, const float* __restrict__ beta,
    const float* __restrict__ gate, const int* __restrict__ cu,
    float* __restrict__ O)
{
    const int b = blockIdx.x >> 4;
    const int h = blockIdx.x & 15;
    const int start = cu[b];
    const int end   = cu[b + 1];

    const int tid = threadIdx.x;
    const int v  = tid >> 2;
    const int kh = tid & 3;

    const int qoff = (h >> 1) * 64;
    const int koff = KEY_DIM + (h >> 1) * 64;
    const int voff = 2 * KEY_DIM + h * 64;

    float S[16];
#pragma unroll
    for (int i = 0; i < 16; i++) S[i] = 0.f;

    __shared__ float sk[RING][64];
    __shared__ float sq[RING][64];
    __shared__ float sv[RING][64];
    __shared__ float sgb[RING][2];

    auto issue = [&](int t, int slot) {
        if (t < end) {
            const float* __restrict__ row = qkv + (size_t)t * CONV_DIM;
            if (tid < 16)       cp16f(&sk[slot][tid * 4],        row + koff + tid * 4);
            else if (tid < 32)  cp16f(&sq[slot][(tid - 16) * 4], row + qoff + (tid - 16) * 4);
            else if (tid < 48)  cp16f(&sv[slot][(tid - 32) * 4], row + voff + (tid - 32) * 4);
            else if (tid == 48) cp4f(&sgb[slot][0], gate + (size_t)t * HV + h);
            else if (tid == 49) cp4f(&sgb[slot][1], beta + (size_t)t * HV + h);
        }
    };

#pragma unroll
    for (int j = 0; j < 4; j++) { issue(start + j, j); CP_COMMIT(); }

    int slot = 0;
    for (int t = start; t < end; t++) {
        cp_wait<3>();
        __syncthreads();

        // refill slot (slot+4)%5 == (slot-1+5)%5 (consumed at step t-1)
        int s4 = slot + 4; if (s4 >= RING) s4 -= RING;
        issue(t + 4, s4);
        CP_COMMIT();

        float kf[16], qf[16];
        const float4* k4 = (const float4*)(&sk[slot][kh * 16]);
        const float4* q4 = (const float4*)(&sq[slot][kh * 16]);
#pragma unroll
        for (int j = 0; j < 4; j++) {
            float4 kv4 = k4[j]; float4 qv4 = q4[j];
            kf[4*j+0]=kv4.x; kf[4*j+1]=kv4.y; kf[4*j+2]=kv4.z; kf[4*j+3]=kv4.w;
            qf[4*j+0]=qv4.x; qf[4*j+1]=qv4.y; qf[4*j+2]=qv4.z; qf[4*j+3]=qv4.w;
        }
        const float cv = sv[slot][v];
        const float cg = expf(sgb[slot][0]);
        const float cb = sgb[slot][1];

        // critical-path dot: dk = k . S
        float dk0=0,dk1=0,dk2=0,dk3=0;
#pragma unroll
        for (int j = 0; j < 4; j++) {
            dk0 = fmaf(kf[4*j+0], S[4*j+0], dk0);
            dk1 = fmaf(kf[4*j+1], S[4*j+1], dk1);
            dk2 = fmaf(kf[4*j+2], S[4*j+2], dk2);
            dk3 = fmaf(kf[4*j+3], S[4*j+3], dk3);
        }
        float dk = (dk0 + dk1) + (dk2 + dk3);
        dk += __shfl_xor_sync(0xffffffffu, dk, 1);
        dk += __shfl_xor_sync(0xffffffffu, dk, 2);

        // off-critical dots (overlap with shfl latency)
        float dq0=0,dq1=0,dq2=0,dq3=0, qk0=0,qk1=0,qk2=0,qk3=0;
#pragma unroll
        for (int j = 0; j < 4; j++) {
            dq0 = fmaf(qf[4*j+0], S[4*j+0], dq0);
            dq1 = fmaf(qf[4*j+1], S[4*j+1], dq1);
            dq2 = fmaf(qf[4*j+2], S[4*j+2], dq2);
            dq3 = fmaf(qf[4*j+3], S[4*j+3], dq3);
            qk0 = fmaf(qf[4*j+0], kf[4*j+0], qk0);
            qk1 = fmaf(qf[4*j+1], kf[4*j+1], qk1);
            qk2 = fmaf(qf[4*j+2], kf[4*j+2], qk2);
            qk3 = fmaf(qf[4*j+3], kf[4*j+3], qk3);
        }
        float dq = (dq0 + dq1) + (dq2 + dq3);
        float qk = (qk0 + qk1) + (qk2 + qk3);

        const float delta = cb * (cv - cg * dk);

#pragma unroll
        for (int i = 0; i < 16; i++)
            S[i] = fmaf(kf[i], delta, cg * S[i]);

        dq += __shfl_xor_sync(0xffffffffu, dq, 1);
        qk += __shfl_xor_sync(0xffffffffu, qk, 1);
        dq += __shfl_xor_sync(0xffffffffu, dq, 2);
        qk += __shfl_xor_sync(0xffffffffu, qk, 2);

        if (kh == 0)
            O[(size_t)t * VAL_DIM + h * 64 + v] = fmaf(qk, delta, cg * dq);

        slot++; if (slot >= RING) slot = 0;
    }
}

// ---------------------------------------------------------------------------
// Gated RMSNorm fused with bf16 split
// ---------------------------------------------------------------------------
__global__ __launch_bounds__(512) void rmsnorm_split_kernel(
    const float* __restrict__ o, const float* __restrict__ z,
    const float* __restrict__ nw, bf16* __restrict__ onh, bf16* __restrict__ onl)
{
    const int t = blockIdx.x;
    const int w = threadIdx.x >> 5;
    const int lane = threadIdx.x & 31;
    const size_t base = (size_t)t * VAL_DIM + w * 64;

    float x0 = o[base + lane];
    float x1 = o[base + 32 + lane];
    float ss = x0 * x0 + x1 * x1;
#pragma unroll
    for (int off = 16; off; off >>= 1)
        ss += __shfl_xor_sync(0xffffffffu, ss, off);
    float r = rsqrtf(ss * (1.f / 64.f) + 1e-6f);

    float z0 = z[base + lane];
    float z1 = z[base + 32 + lane];
    float s0 = z0 / (1.f + expf(-z0));
    float s1 = z1 / (1.f + expf(-z1));

    float v0 = x0 * r * nw[lane]      * s0;
    float v1 = x1 * r * nw[lane + 32] * s1;

    bf16 h0 = __float2bfloat16(v0);
    bf16 h1 = __float2bfloat16(v1);
    onh[base + lane]      = h0;
    onh[base + 32 + lane] = h1;
    onl[base + lane]      = __float2bfloat16(v0 - __bfloat162float(h0));
    onl[base + 32 + lane] = __float2bfloat16(v1 - __bfloat162float(h1));
}

// ---------------------------------------------------------------------------
extern "C" void kernel_launch(void* const* d_in, const int* in_sizes, int n_in,
                              void* d_out, int out_size)
{
    const float* hs     = (const float*)d_in[0];
    const float* W_qkv  = (const float*)d_in[1];
    const float* W_z    = (const float*)d_in[2];
    const float* W_b    = (const float*)d_in[3];
    const float* W_a    = (const float*)d_in[4];
    const float* conv_w = (const float*)d_in[5];
    const float* dt_b   = (const float*)d_in[6];
    const float* A_log  = (const float*)d_in[7];
    const float* norm_w = (const float*)d_in[8];
    const float* W_out  = (const float*)d_in[9];
    const int*   cu     = (const int*)d_in[10];

    const int total = in_sizes[0] / HIDDEN;       // 1536
    const int B     = in_sizes[10] - 1;           // 4

    float *mixed, *qkv, *zbuf, *c3, *betab, *gateb, *obuf;
    bf16 *hs_h, *hs_l, *wqkv_h, *wqkv_l, *wz_h, *wz_l, *wba_h, *wba_l,
         *wout_h, *wout_l, *on_h, *on_l;
    cudaGetSymbolAddress((void**)&mixed,  g_mixed);
    cudaGetSymbolAddress((void**)&qkv,    g_qkv);
    cudaGetSymbolAddress((void**)&zbuf,   g_z);
    cudaGetSymbolAddress((void**)&c3,     g_c3);
    cudaGetSymbolAddress((void**)&betab,  g_beta);
    cudaGetSymbolAddress((void**)&gateb,  g_gate);
    cudaGetSymbolAddress((void**)&obuf,   g_o);
    cudaGetSymbolAddress((void**)&hs_h,   g_hs_h);
    cudaGetSymbolAddress((void**)&hs_l,   g_hs_l);
    cudaGetSymbolAddress((void**)&wqkv_h, g_wqkv_h);
    cudaGetSymbolAddress((void**)&wqkv_l, g_wqkv_l);
    cudaGetSymbolAddress((void**)&wz_h,   g_wz_h);
    cudaGetSymbolAddress((void**)&wz_l,   g_wz_l);
    cudaGetSymbolAddress((void**)&wba_h,  g_wba_h);
    cudaGetSymbolAddress((void**)&wba_l,  g_wba_l);
    cudaGetSymbolAddress((void**)&wout_h, g_wout_h);
    cudaGetSymbolAddress((void**)&wout_l, g_wout_l);
    cudaGetSymbolAddress((void**)&on_h,   g_on_h);
    cudaGetSymbolAddress((void**)&on_l,   g_on_l);

    // 0) hs split
    split4_kernel<<<(total * HIDDEN / 4 + 255) / 256, 256>>>(
        (const float4*)hs, (uint2*)hs_h, (uint2*)hs_l, total * HIDDEN / 4);
    // 1) W_qkv split
    split4_kernel<<<(CONV_DIM * HIDDEN / 4 + 255) / 256, 256>>>(
        (const float4*)W_qkv, (uint2*)wqkv_h, (uint2*)wqkv_l, CONV_DIM * HIDDEN / 4);
    // 2) W_z + W_out + W_ba splits (combined)
    split_weights2_kernel<<<(NZ4 + NO4 + NBA4 + 255) / 256, 256>>>(
        (const float4*)W_z, (const float4*)W_out, W_b, W_a,
        (uint2*)wz_h, (uint2*)wz_l, (uint2*)wout_h, (uint2*)wout_l,
        (uint2*)wba_h, (uint2*)wba_l);

    // 3) fused projections: [W_qkv | W_z | W_ba-padded] -> mixed, z, c3
    //    (launch index 3 = ncu capture slot)
    gemm_bf16split_tri<<<dim3((CONV_DIM + VAL_DIM + 128) / 128, total / 128), 256>>>(
        hs_h, hs_l, wqkv_h, wqkv_l, wz_h, wz_l, wba_h, wba_l,
        mixed, zbuf, c3, CONV_DIM, VAL_DIM, 128);

    // 4) beta / gate
    ba_finish_kernel<<<(total * 32 + 255) / 256, 256>>>(c3, dt_b, A_log, betab, gateb, total);

    // 5) fused causal conv + silu + qk norm
    conv_norm_kernel<<<total, 256>>>(mixed, conv_w, cu, B, qkv);

    // 6) gated delta rule recurrence
    recurrence_kernel<<<B * HV, 256>>>(qkv, betab, gateb, cu, obuf);

    // 7) gated RMSNorm + split
    rmsnorm_split_kernel<<<total, 512>>>(obuf, zbuf, norm_w, on_h, on_l);

    // 8) output projection -> d_out
    gemm_bf16split_tri<<<dim3(HIDDEN / 128, total / 128), 256>>>(
        on_h, on_l, wout_h, wout_l, wout_h, wout_l, wout_h, wout_l,
        (float*)d_out, (float*)d_out, (float*)d_out, HIDDEN, 0, 0);
}

// round 7
// speedup vs baseline: 1.6694x; 1.0076x over previous
#include <cuda_runtime.h>
#include <cuda_bf16.h>
#include <math.h>
#include <stdint.h>

// ---------------------------------------------------------------------------
// GatedDeltaNetVarlen — round 7:
//   * recurrence inner math converted to packed f32x2 (Blackwell FFMA2):
//     halves the FMA-pipe issue floor; pairs alias smem directly (no packing)
//   * GEMM / splits / conv / rmsnorm identical to R6 (proven)
// ---------------------------------------------------------------------------

#define TOTAL_MAX 1536
#define HIDDEN    1024
#define CONV_DIM  2048
#define KEY_DIM   512
#define VAL_DIM   1024
#define HV        16
#define GK        1024
#define SSTR      40     // smem row stride (bf16), conflict-free for LDSM

typedef __nv_bfloat16 bf16;
typedef unsigned long long ull;

__device__ float g_mixed[TOTAL_MAX * CONV_DIM];
__device__ float g_qkv  [TOTAL_MAX * CONV_DIM];
__device__ float g_z    [TOTAL_MAX * VAL_DIM];
__device__ float g_c3   [TOTAL_MAX * 128];
__device__ float g_beta [TOTAL_MAX * HV];
__device__ float g_gate [TOTAL_MAX * HV];
__device__ float g_o    [TOTAL_MAX * VAL_DIM];

__device__ bf16 g_hs_h  [TOTAL_MAX * HIDDEN];
__device__ bf16 g_hs_l  [TOTAL_MAX * HIDDEN];
__device__ bf16 g_wqkv_h[CONV_DIM * HIDDEN];
__device__ bf16 g_wqkv_l[CONV_DIM * HIDDEN];
__device__ bf16 g_wz_h  [VAL_DIM * HIDDEN];
__device__ bf16 g_wz_l  [VAL_DIM * HIDDEN];
__device__ bf16 g_wba_h [128 * HIDDEN];
__device__ bf16 g_wba_l [128 * HIDDEN];
__device__ bf16 g_wout_h[HIDDEN * VAL_DIM];
__device__ bf16 g_wout_l[HIDDEN * VAL_DIM];
__device__ bf16 g_on_h  [TOTAL_MAX * VAL_DIM];
__device__ bf16 g_on_l  [TOTAL_MAX * VAL_DIM];

// ---------------------------------------------------------------------------
// helpers
// ---------------------------------------------------------------------------
__device__ __forceinline__ void ldsm_x4(unsigned& r0, unsigned& r1, unsigned& r2, unsigned& r3,
                                        const bf16* p)
{
    unsigned addr = (unsigned)__cvta_generic_to_shared(p);
    asm volatile("ldmatrix.sync.aligned.m8n8.x4.shared.b16 {%0,%1,%2,%3}, [%4];"
                 : "=r"(r0), "=r"(r1), "=r"(r2), "=r"(r3) : "r"(addr));
}

__device__ __forceinline__ void mma16816(float* c, const unsigned* a, const unsigned* b)
{
    asm volatile(
        "mma.sync.aligned.m16n8k16.row.col.f32.bf16.bf16.f32 "
        "{%0,%1,%2,%3},{%4,%5,%6,%7},{%8,%9},{%0,%1,%2,%3};\n"
        : "+f"(c[0]), "+f"(c[1]), "+f"(c[2]), "+f"(c[3])
        : "r"(a[0]), "r"(a[1]), "r"(a[2]), "r"(a[3]), "r"(b[0]), "r"(b[1]));
}

__device__ __forceinline__ void cp16f(const float* dst_smem, const float* src)
{
    unsigned d = (unsigned)__cvta_generic_to_shared(dst_smem);
    asm volatile("cp.async.cg.shared.global [%0], [%1], 16;" :: "r"(d), "l"(src));
}
__device__ __forceinline__ void cp4f(const float* dst_smem, const float* src)
{
    unsigned d = (unsigned)__cvta_generic_to_shared(dst_smem);
    asm volatile("cp.async.ca.shared.global [%0], [%1], 4;" :: "r"(d), "l"(src));
}
#define CP_COMMIT() asm volatile("cp.async.commit_group;")
template<int N> __device__ __forceinline__ void cp_wait() {
    asm volatile("cp.async.wait_group %0;" :: "n"(N));
}

// packed f32x2 ops (Blackwell)
__device__ __forceinline__ ull fma2(ull a, ull b, ull c) {
    ull d; asm("fma.rn.f32x2 %0, %1, %2, %3;" : "=l"(d) : "l"(a), "l"(b), "l"(c)); return d;
}
__device__ __forceinline__ ull mul2(ull a, ull b) {
    ull d; asm("mul.rn.f32x2 %0, %1, %2;" : "=l"(d) : "l"(a), "l"(b)); return d;
}
__device__ __forceinline__ ull pk2(float lo, float hi) {
    ull r; asm("mov.b64 %0, {%1,%2};" : "=l"(r) : "f"(lo), "f"(hi)); return r;
}
__device__ __forceinline__ void upk2(ull p, float& lo, float& hi) {
    asm("mov.b64 {%0,%1}, %2;" : "=f"(lo), "=f"(hi) : "l"(p));
}

// ---------------------------------------------------------------------------
// bf16 split GEMM, triple N-range (proven R3/R6 kernel)
// ---------------------------------------------------------------------------
__global__ __launch_bounds__(256) void gemm_bf16split_tri(
    const bf16* __restrict__ Ah, const bf16* __restrict__ Al,
    const bf16* __restrict__ B1h, const bf16* __restrict__ B1l,
    const bf16* __restrict__ B2h, const bf16* __restrict__ B2l,
    const bf16* __restrict__ B3h, const bf16* __restrict__ B3l,
    float* __restrict__ C1, float* __restrict__ C2, float* __restrict__ C3,
    int N1, int N2, int N3)
{
    __shared__ bf16 As[2][128][SSTR];
    __shared__ bf16 Bs[2][128][SSTR];

    const int tid  = threadIdx.x;
    const int lane = tid & 31;
    const int wid  = tid >> 5;
    const int wm   = wid & 3;
    const int wn   = wid >> 2;
    const int bm   = blockIdx.y * 128;
    const int bnG  = blockIdx.x * 128;

    const bf16* Bh; const bf16* Bl; float* C; int bn, ldc;
    if (bnG < N1)           { Bh = B1h; Bl = B1l; C = C1; bn = bnG;           ldc = N1; }
    else if (bnG < N1 + N2) { Bh = B2h; Bl = B2l; C = C2; bn = bnG - N1;      ldc = N2; }
    else                    { Bh = B3h; Bl = B3l; C = C3; bn = bnG - N1 - N2; ldc = N3; }

    const int lrow = tid >> 2;
    const int lcol = (tid & 3) * 8;

    const bf16* APs[3] = { Ah, Al, Ah };
    const bf16* BPs[3] = { Bh, Bh, Bl };

    float c[2][8][4];
#pragma unroll
    for (int mi = 0; mi < 2; mi++)
#pragma unroll
        for (int ni = 0; ni < 8; ni++)
#pragma unroll
            for (int r = 0; r < 4; r++) c[mi][ni][r] = 0.f;

    const int NIT = 3 * (GK / 32);

    {
        uint4 pa0 = *(const uint4*)(APs[0] + (size_t)(bm + lrow) * GK + lcol);
        uint4 pa1 = *(const uint4*)(APs[0] + (size_t)(bm + lrow + 64) * GK + lcol);
        uint4 pb0 = *(const uint4*)(BPs[0] + (size_t)(bn + lrow) * GK + lcol);
        uint4 pb1 = *(const uint4*)(BPs[0] + (size_t)(bn + lrow + 64) * GK + lcol);
        *(uint4*)&As[0][lrow][lcol]      = pa0;
        *(uint4*)&As[0][lrow + 64][lcol] = pa1;
        *(uint4*)&Bs[0][lrow][lcol]      = pb0;
        *(uint4*)&Bs[0][lrow + 64][lcol] = pb1;
    }
    __syncthreads();

    const int lrow16 = lane & 15;
    const int lhalf  = lane >> 4;
    const int l8     = lane & 7;
    const int grp    = lane >> 3;

    for (int it = 0; it < NIT; ++it) {
        const int cur = it & 1;
        const bool has_next = (it + 1 < NIT);

        uint4 pa0, pa1, pb0, pb1;
        if (has_next) {
            const int nit = it + 1;
            const int p  = nit >> 5;
            const int k0 = (nit & 31) * 32;
            pa0 = *(const uint4*)(APs[p] + (size_t)(bm + lrow) * GK + k0 + lcol);
            pa1 = *(const uint4*)(APs[p] + (size_t)(bm + lrow + 64) * GK + k0 + lcol);
            pb0 = *(const uint4*)(BPs[p] + (size_t)(bn + lrow) * GK + k0 + lcol);
            pb1 = *(const uint4*)(BPs[p] + (size_t)(bn + lrow + 64) * GK + k0 + lcol);
        }

#pragma unroll
        for (int kk = 0; kk < 32; kk += 16) {
            unsigned a[2][4];
#pragma unroll
            for (int mi = 0; mi < 2; mi++)
                ldsm_x4(a[mi][0], a[mi][1], a[mi][2], a[mi][3],
                        &As[cur][wm * 32 + mi * 16 + lrow16][kk + 8 * lhalf]);
            unsigned b[8][2];
#pragma unroll
            for (int nj = 0; nj < 4; nj++)
                ldsm_x4(b[2 * nj][0], b[2 * nj][1], b[2 * nj + 1][0], b[2 * nj + 1][1],
                        &Bs[cur][wn * 64 + nj * 16 + (grp >> 1) * 8 + l8][kk + 8 * (grp & 1)]);
#pragma unroll
            for (int mi = 0; mi < 2; mi++)
#pragma unroll
                for (int ni = 0; ni < 8; ni++)
                    mma16816(c[mi][ni], a[mi], b[ni]);
        }

        if (has_next) {
            const int nxt = cur ^ 1;
            *(uint4*)&As[nxt][lrow][lcol]      = pa0;
            *(uint4*)&As[nxt][lrow + 64][lcol] = pa1;
            *(uint4*)&Bs[nxt][lrow][lcol]      = pb0;
            *(uint4*)&Bs[nxt][lrow + 64][lcol] = pb1;
            __syncthreads();
        }
    }

    const int g  = lane >> 2;
    const int t4 = lane & 3;
#pragma unroll
    for (int mi = 0; mi < 2; mi++) {
        const int row0 = bm + wm * 32 + mi * 16 + g;
#pragma unroll
        for (int ni = 0; ni < 8; ni++) {
            const int col = bn + wn * 64 + ni * 8 + 2 * t4;
            *(float2*)(C + (size_t)row0 * ldc + col)       = make_float2(c[mi][ni][0], c[mi][ni][1]);
            *(float2*)(C + (size_t)(row0 + 8) * ldc + col) = make_float2(c[mi][ni][2], c[mi][ni][3]);
        }
    }
}

// ---------------------------------------------------------------------------
// Vectorized fp32 -> (hi,lo) bf16 split
// ---------------------------------------------------------------------------
__device__ __forceinline__ void split_one4(float4 v, uint2* h, uint2* l, int i)
{
    bf16 h0 = __float2bfloat16(v.x), h1 = __float2bfloat16(v.y);
    bf16 h2 = __float2bfloat16(v.z), h3 = __float2bfloat16(v.w);
    bf16 l0 = __float2bfloat16(v.x - __bfloat162float(h0));
    bf16 l1 = __float2bfloat16(v.y - __bfloat162float(h1));
    bf16 l2 = __float2bfloat16(v.z - __bfloat162float(h2));
    bf16 l3 = __float2bfloat16(v.w - __bfloat162float(h3));
    uint2 hv, lv;
    hv.x = ((unsigned)__bfloat16_as_ushort(h1) << 16) | __bfloat16_as_ushort(h0);
    hv.y = ((unsigned)__bfloat16_as_ushort(h3) << 16) | __bfloat16_as_ushort(h2);
    lv.x = ((unsigned)__bfloat16_as_ushort(l1) << 16) | __bfloat16_as_ushort(l0);
    lv.y = ((unsigned)__bfloat16_as_ushort(l3) << 16) | __bfloat16_as_ushort(l2);
    h[i] = hv;
    l[i] = lv;
}

__global__ __launch_bounds__(256) void split4_kernel(
    const float4* __restrict__ x, uint2* __restrict__ h, uint2* __restrict__ l, int n4)
{
    int i = blockIdx.x * blockDim.x + threadIdx.x;
    if (i >= n4) return;
    split_one4(x[i], h, l, i);
}

// Combined split of W_z, W_out, and padded [W_b;W_a;0] (one launch)
#define NZ4  (VAL_DIM * HIDDEN / 4)
#define NO4  (HIDDEN * VAL_DIM / 4)
#define NBA4 (128 * HIDDEN / 4)
__global__ __launch_bounds__(256) void split_weights2_kernel(
    const float4* __restrict__ wz, const float4* __restrict__ wout,
    const float* __restrict__ Wb, const float* __restrict__ Wa,
    uint2* __restrict__ wzh, uint2* __restrict__ wzl,
    uint2* __restrict__ wouth, uint2* __restrict__ woutl,
    uint2* __restrict__ wbah, uint2* __restrict__ wbal)
{
    int i = blockIdx.x * blockDim.x + threadIdx.x;
    if (i < NZ4) {
        split_one4(wz[i], wzh, wzl, i);
    } else if (i < NZ4 + NO4) {
        int j = i - NZ4;
        split_one4(wout[j], wouth, woutl, j);
    } else if (i < NZ4 + NO4 + NBA4) {
        int j = i - NZ4 - NO4;
        int e = j * 4;
        float4 v;
        if (e < 16 * HIDDEN)      v = *(const float4*)(Wb + e);
        else if (e < 32 * HIDDEN) v = *(const float4*)(Wa + e - 16 * HIDDEN);
        else                      v = make_float4(0.f, 0.f, 0.f, 0.f);
        split_one4(v, wbah, wbal, j);
    }
}

// beta / gate from the GEMM's third range
__global__ __launch_bounds__(256) void ba_finish_kernel(
    const float* __restrict__ c3, const float* __restrict__ dtb,
    const float* __restrict__ Alog, float* __restrict__ beta, float* __restrict__ gate,
    int total)
{
    int idx = blockIdx.x * blockDim.x + threadIdx.x;
    int t = idx >> 5;
    int o = idx & 31;
    if (t >= total) return;
    float x = c3[(size_t)t * 128 + o];
    if (o < HV) {
        beta[(size_t)t * HV + o] = 1.f / (1.f + expf(-x));
    } else {
        int hh = o - HV;
        float xv = x + dtb[hh];
        float sp = (xv > 20.f) ? xv : log1pf(expf(xv));
        gate[(size_t)t * HV + hh] = -expf(Alog[hh]) * sp;
    }
}

// ---------------------------------------------------------------------------
// Fused causal depthwise conv(4) + silu + per-head q/k L2 norm
// ---------------------------------------------------------------------------
__global__ __launch_bounds__(256) void conv_norm_kernel(
    const float* __restrict__ mixed, const float* __restrict__ cw,
    const int* __restrict__ cu, int B, float* __restrict__ out)
{
    const int t = blockIdx.x;
    const int tid = threadIdx.x;
    const int c0 = tid * 8;

    int start = 0;
    for (int i = 1; i < B; i++) { int s = cu[i]; if (t >= s) start = s; }

    float y[8];
#pragma unroll
    for (int j = 0; j < 8; j++) {
        const int c = c0 + j;
        const float4 w4 = *(const float4*)(cw + c * 4);
        float acc = mixed[(size_t)t * CONV_DIM + c] * w4.w;
        if (t - 1 >= start) acc = fmaf(mixed[(size_t)(t - 1) * CONV_DIM + c], w4.z, acc);
        if (t - 2 >= start) acc = fmaf(mixed[(size_t)(t - 2) * CONV_DIM + c], w4.y, acc);
        if (t - 3 >= start) acc = fmaf(mixed[(size_t)(t - 3) * CONV_DIM + c], w4.x, acc);
        y[j] = acc / (1.f + expf(-acc));
    }

    if (c0 < 2 * KEY_DIM) {
        float ss = 0.f;
#pragma unroll
        for (int j = 0; j < 8; j++) ss = fmaf(y[j], y[j], ss);
        ss += __shfl_xor_sync(0xffffffffu, ss, 1);
        ss += __shfl_xor_sync(0xffffffffu, ss, 2);
        ss += __shfl_xor_sync(0xffffffffu, ss, 4);
        float r = rsqrtf(ss + 1e-6f);
        if (c0 < KEY_DIM) r *= 0.125f;
#pragma unroll
        for (int j = 0; j < 8; j++) y[j] *= r;
    }

    float4* dst = (float4*)(out + (size_t)t * CONV_DIM + c0);
    dst[0] = make_float4(y[0], y[1], y[2], y[3]);
    dst[1] = make_float4(y[4], y[5], y[6], y[7]);
}

// ---------------------------------------------------------------------------
// Gated delta rule recurrence: cp.async 5-slot ring + packed f32x2 math.
// One block per (seq,head), 256 threads (v=tid>>2, kh=tid&3).
// ---------------------------------------------------------------------------
#define RING 5
__global__ __launch_bounds__(256) void recurrence_kernel(
    const float* __restrict__ qkv, const float* __restrict__ beta,
    const float* __restrict__ gate, const int* __restrict__ cu,
    float* __restrict__ O)
{
    const int b = blockIdx.x >> 4;
    const int h = blockIdx.x & 15;
    const int start = cu[b];
    const int end   = cu[b + 1];

    const int tid = threadIdx.x;
    const int v  = tid >> 2;
    const int kh = tid & 3;

    const int qoff = (h >> 1) * 64;
    const int koff = KEY_DIM + (h >> 1) * 64;
    const int voff = 2 * KEY_DIM + h * 64;

    ull S2[8];
#pragma unroll
    for (int i = 0; i < 8; i++) S2[i] = 0ull;

    __shared__ __align__(16) float sk[RING][64];
    __shared__ __align__(16) float sq[RING][64];
    __shared__ __align__(16) float sv[RING][64];
    __shared__ float sgb[RING][2];

    auto issue = [&](int t, int slot) {
        if (t < end) {
            const float* __restrict__ row = qkv + (size_t)t * CONV_DIM;
            if (tid < 16)       cp16f(&sk[slot][tid * 4],        row + koff + tid * 4);
            else if (tid < 32)  cp16f(&sq[slot][(tid - 16) * 4], row + qoff + (tid - 16) * 4);
            else if (tid < 48)  cp16f(&sv[slot][(tid - 32) * 4], row + voff + (tid - 32) * 4);
            else if (tid == 48) cp4f(&sgb[slot][0], gate + (size_t)t * HV + h);
            else if (tid == 49) cp4f(&sgb[slot][1], beta + (size_t)t * HV + h);
        }
    };

#pragma unroll
    for (int j = 0; j < 4; j++) { issue(start + j, j); CP_COMMIT(); }

    int slot = 0;
    for (int t = start; t < end; t++) {
        cp_wait<3>();
        __syncthreads();

        int s4 = slot + 4; if (s4 >= RING) s4 -= RING;
        issue(t + 4, s4);
        CP_COMMIT();

        // load k/q pairs directly as packed f32x2 (16B aligned)
        ull k2[8], q2[8];
        const ulonglong2* k4 = (const ulonglong2*)(&sk[slot][kh * 16]);
        const ulonglong2* q4 = (const ulonglong2*)(&sq[slot][kh * 16]);
#pragma unroll
        for (int j = 0; j < 4; j++) {
            ulonglong2 kk = k4[j]; ulonglong2 qq = q4[j];
            k2[2*j] = kk.x; k2[2*j+1] = kk.y;
            q2[2*j] = qq.x; q2[2*j+1] = qq.y;
        }
        const float cv = sv[slot][v];
        const float cg = expf(sgb[slot][0]);
        const float cb = sgb[slot][1];

        // critical-path dot: dk = k . S (packed, 4-acc ILP)
        ull a0 = 0, a1 = 0, a2 = 0, a3 = 0;
#pragma unroll
        for (int j = 0; j < 2; j++) {
            a0 = fma2(k2[4*j+0], S2[4*j+0], a0);
            a1 = fma2(k2[4*j+1], S2[4*j+1], a1);
            a2 = fma2(k2[4*j+2], S2[4*j+2], a2);
            a3 = fma2(k2[4*j+3], S2[4*j+3], a3);
        }
        float x0, x1, y0, y1, z0, z1, w0, w1;
        upk2(a0, x0, x1); upk2(a1, y0, y1); upk2(a2, z0, z1); upk2(a3, w0, w1);
        float dk = ((x0 + x1) + (y0 + y1)) + ((z0 + z1) + (w0 + w1));
        dk += __shfl_xor_sync(0xffffffffu, dk, 1);
        dk += __shfl_xor_sync(0xffffffffu, dk, 2);

        // off-critical dots (overlap with shfl latency)
        ull b0 = 0, b1 = 0, b2 = 0, b3 = 0;   // dq = q.S
        ull c0 = 0, c1 = 0, c2 = 0, c3 = 0;   // qk = q.k
#pragma unroll
        for (int j = 0; j < 2; j++) {
            b0 = fma2(q2[4*j+0], S2[4*j+0], b0);
            b1 = fma2(q2[4*j+1], S2[4*j+1], b1);
            b2 = fma2(q2[4*j+2], S2[4*j+2], b2);
            b3 = fma2(q2[4*j+3], S2[4*j+3], b3);
            c0 = fma2(q2[4*j+0], k2[4*j+0], c0);
            c1 = fma2(q2[4*j+1], k2[4*j+1], c1);
            c2 = fma2(q2[4*j+2], k2[4*j+2], c2);
            c3 = fma2(q2[4*j+3], k2[4*j+3], c3);
        }

        const float delta = cb * (cv - cg * dk);
        const ull cg2 = pk2(cg, cg);
        const ull dl2 = pk2(delta, delta);

#pragma unroll
        for (int i = 0; i < 8; i++)
            S2[i] = fma2(k2[i], dl2, mul2(cg2, S2[i]));

        upk2(b0, x0, x1); upk2(b1, y0, y1); upk2(b2, z0, z1); upk2(b3, w0, w1);
        float dq = ((x0 + x1) + (y0 + y1)) + ((z0 + z1) + (w0 + w1));
        upk2(c0, x0, x1); upk2(c1, y0, y1); upk2(c2, z0, z1); upk2(c3, w0, w1);
        float qk = ((x0 + x1) + (y0 + y1)) + ((z0 + z1) + (w0 + w1));

        dq += __shfl_xor_sync(0xffffffffu, dq, 1);
        qk += __shfl_xor_sync(0xffffffffu, qk, 1);
        dq += __shfl_xor_sync(0xffffffffu, dq, 2);
        qk += __shfl_xor_sync(0xffffffffu, qk, 2);

        if (kh == 0)
            O[(size_t)t * VAL_DIM + h * 64 + v] = fmaf(qk, delta, cg * dq);

        slot++; if (slot >= RING) slot = 0;
    }
}

// ---------------------------------------------------------------------------
// Gated RMSNorm fused with bf16 split
// ---------------------------------------------------------------------------
__global__ __launch_bounds__(512) void rmsnorm_split_kernel(
    const float* __restrict__ o, const float* __restrict__ z,
    const float* __restrict__ nw, bf16* __restrict__ onh, bf16* __restrict__ onl)
{
    const int t = blockIdx.x;
    const int w = threadIdx.x >> 5;
    const int lane = threadIdx.x & 31;
    const size_t base = (size_t)t * VAL_DIM + w * 64;

    float x0 = o[base + lane];
    float x1 = o[base + 32 + lane];
    float ss = x0 * x0 + x1 * x1;
#pragma unroll
    for (int off = 16; off; off >>= 1)
        ss += __shfl_xor_sync(0xffffffffu, ss, off);
    float r = rsqrtf(ss * (1.f / 64.f) + 1e-6f);

    float z0 = z[base + lane];
    float z1 = z[base + 32 + lane];
    float s0 = z0 / (1.f + expf(-z0));
    float s1 = z1 / (1.f + expf(-z1));

    float v0 = x0 * r * nw[lane]      * s0;
    float v1 = x1 * r * nw[lane + 32] * s1;

    bf16 h0 = __float2bfloat16(v0);
    bf16 h1 = __float2bfloat16(v1);
    onh[base + lane]      = h0;
    onh[base + 32 + lane] = h1;
    onl[base + lane]      = __float2bfloat16(v0 - __bfloat162float(h0));
    onl[base + 32 + lane] = __float2bfloat16(v1 - __bfloat162float(h1));
}

// ---------------------------------------------------------------------------
extern "C" void kernel_launch(void* const* d_in, const int* in_sizes, int n_in,
                              void* d_out, int out_size)
{
    const float* hs     = (const float*)d_in[0];
    const float* W_qkv  = (const float*)d_in[1];
    const float* W_z    = (const float*)d_in[2];
    const float* W_b    = (const float*)d_in[3];
    const float* W_a    = (const float*)d_in[4];
    const float* conv_w = (const float*)d_in[5];
    const float* dt_b   = (const float*)d_in[6];
    const float* A_log  = (const float*)d_in[7];
    const float* norm_w = (const float*)d_in[8];
    const float* W_out  = (const float*)d_in[9];
    const int*   cu     = (const int*)d_in[10];

    const int total = in_sizes[0] / HIDDEN;       // 1536
    const int B     = in_sizes[10] - 1;           // 4

    float *mixed, *qkv, *zbuf, *c3, *betab, *gateb, *obuf;
    bf16 *hs_h, *hs_l, *wqkv_h, *wqkv_l, *wz_h, *wz_l, *wba_h, *wba_l,
         *wout_h, *wout_l, *on_h, *on_l;
    cudaGetSymbolAddress((void**)&mixed,  g_mixed);
    cudaGetSymbolAddress((void**)&qkv,    g_qkv);
    cudaGetSymbolAddress((void**)&zbuf,   g_z);
    cudaGetSymbolAddress((void**)&c3,     g_c3);
    cudaGetSymbolAddress((void**)&betab,  g_beta);
    cudaGetSymbolAddress((void**)&gateb,  g_gate);
    cudaGetSymbolAddress((void**)&obuf,   g_o);
    cudaGetSymbolAddress((void**)&hs_h,   g_hs_h);
    cudaGetSymbolAddress((void**)&hs_l,   g_hs_l);
    cudaGetSymbolAddress((void**)&wqkv_h, g_wqkv_h);
    cudaGetSymbolAddress((void**)&wqkv_l, g_wqkv_l);
    cudaGetSymbolAddress((void**)&wz_h,   g_wz_h);
    cudaGetSymbolAddress((void**)&wz_l,   g_wz_l);
    cudaGetSymbolAddress((void**)&wba_h,  g_wba_h);
    cudaGetSymbolAddress((void**)&wba_l,  g_wba_l);
    cudaGetSymbolAddress((void**)&wout_h, g_wout_h);
    cudaGetSymbolAddress((void**)&wout_l, g_wout_l);
    cudaGetSymbolAddress((void**)&on_h,   g_on_h);
    cudaGetSymbolAddress((void**)&on_l,   g_on_l);

    // 0) hs split
    split4_kernel<<<(total * HIDDEN / 4 + 255) / 256, 256>>>(
        (const float4*)hs, (uint2*)hs_h, (uint2*)hs_l, total * HIDDEN / 4);
    // 1) W_qkv split
    split4_kernel<<<(CONV_DIM * HIDDEN / 4 + 255) / 256, 256>>>(
        (const float4*)W_qkv, (uint2*)wqkv_h, (uint2*)wqkv_l, CONV_DIM * HIDDEN / 4);
    // 2) W_z + W_out + W_ba splits (combined)
    split_weights2_kernel<<<(NZ4 + NO4 + NBA4 + 255) / 256, 256>>>(
        (const float4*)W_z, (const float4*)W_out, W_b, W_a,
        (uint2*)wz_h, (uint2*)wz_l, (uint2*)wout_h, (uint2*)wout_l,
        (uint2*)wba_h, (uint2*)wba_l);

    // 3) fused projections: [W_qkv | W_z | W_ba-padded] -> mixed, z, c3
    gemm_bf16split_tri<<<dim3((CONV_DIM + VAL_DIM + 128) / 128, total / 128), 256>>>(
        hs_h, hs_l, wqkv_h, wqkv_l, wz_h, wz_l, wba_h, wba_l,
        mixed, zbuf, c3, CONV_DIM, VAL_DIM, 128);

    // 4) beta / gate
    ba_finish_kernel<<<(total * 32 + 255) / 256, 256>>>(c3, dt_b, A_log, betab, gateb, total);

    // 5) fused causal conv + silu + qk norm
    conv_norm_kernel<<<total, 256>>>(mixed, conv_w, cu, B, qkv);

    // 6) gated delta rule recurrence
    recurrence_kernel<<<B * HV, 256>>>(qkv, betab, gateb, cu, obuf);

    // 7) gated RMSNorm + split
    rmsnorm_split_kernel<<<total, 512>>>(obuf, zbuf, norm_w, on_h, on_l);

    // 8) output projection -> d_out
    gemm_bf16split_tri<<<dim3(HIDDEN / 128, total / 128), 256>>>(
        on_h, on_l, wout_h, wout_l, wout_h, wout_l, wout_h, wout_l,
        (float*)d_out, (float*)d_out, (float*)d_out, HIDDEN, 0, 0);
}